// round 3
// baseline (speedup 1.0000x reference)
#include <cuda_runtime.h>

#define CC   10
#define NBIN 49
#define HH   34
#define WW   34
#define HW   (HH * WW)          // 1156
#define SLICE (HW * CC)         // 11560 floats = 46240 B
#define KDIM (CC * NBIN)        // 490
#define NMAX 30000
#define BLK  1024

// Scratch (static device allocation is allowed)
__device__ float g_out_t[KDIM * NMAX];     // [k = c*49+bin][n]

// ---------------------------------------------------------------------------
// Kernel B: per (roi, bin). Stages the bin's 34x34x10 slice into smem in
// [pos][c] layout directly from ft (fused transpose), then builds the
// separable 3x3 stencil  W9 = WY (x) WX - CY (x) CX,  cnt = cntY*cntX,
// and applies it to 10 channels.
// ---------------------------------------------------------------------------
__global__ __launch_bounds__(BLK) void k_roi(const float* __restrict__ ft,
                                             const float* __restrict__ rois, int N) {
    __shared__ float sm[SLICE];
    const int bin = blockIdx.y;

    // Fused staging: ft[(c*49+bin)*1156 + pos] -> sm[pos*10 + c]
    // Reads coalesced (pos contiguous per lane), writes stride-10 STS
    // (gcd(10,32)=2 -> only 2-way bank conflict).
    {
        const int base_in = bin * HW;
        for (int i = threadIdx.x; i < SLICE; i += BLK) {
            int c   = i / HW;            // const-div -> mul
            int pos = i - c * HW;
            sm[pos * CC + c] = ft[c * (NBIN * HW) + base_in + pos];
        }
    }
    __syncthreads();

    const int n = blockIdx.x * BLK + threadIdx.x;
    if (n >= N) return;

    const int ph = bin / 7, pw = bin % 7;

    float rsw = __ldg(rois + n * 5 + 1) * 0.125f;
    float rsh = __ldg(rois + n * 5 + 2) * 0.125f;
    float rew = __ldg(rois + n * 5 + 3) * 0.125f;
    float reh = __ldg(rois + n * 5 + 4) * 0.125f;
    float rh = reh - rsh; rh = (rh > 0.1f) ? rh : 0.1f;
    float rw = rew - rsw; rw = (rw > 0.1f) ? rw : 0.1f;
    float bsh = rh / 7.0f, bsw = rw / 7.0f;
    float sub_h = bsh * 0.25f, sub_w = bsw * 0.25f;
    float hstart = floorf(rsh + (float)ph * bsh);
    float wstart = floorf(rsw + (float)pw * bsw);

    // 3x3 window anchor; all clipped taps land in [X0..X0+2]x[Y0..Y0+2].
    const int X0 = (int)fminf(fmaxf(wstart, 0.f), (float)(WW - 3));
    const int Y0 = (int)fminf(fmaxf(hstart, 0.f), (float)(HH - 3));

    // ---- Y pass (4 iters) ----
    float WY0 = 0.f, WY1 = 0.f, WY2 = 0.f;
    float CY0 = 0.f, CY1 = 0.f, CY2 = 0.f;
    float cntY = 0.f;
#pragma unroll
    for (int ih = 0; ih < 4; ih++) {
        float h = hstart + ((float)ih + 0.5f) * sub_h;
        bool hok = (h > -1.f) && (h < (float)HH);
        float y1f = floorf(h), y2f = ceilf(h);
        bool yv = ((y1f >= 0.f) && (y1f < (float)HH)) ||
                  ((y2f >= 0.f) && (y2f < (float)HH));
        float y1c = fminf(fmaxf(y1f, 0.f), 33.f);
        float y2c = fminf(fmaxf(y2f, 0.f), 33.f);
        float dy = h - y1c;                  // clipped y1 (matches reference)
        int ry1 = (int)y1c - Y0;
        int ry2 = (int)y2c - Y0;
        float hokf = hok ? 1.f : 0.f;
        cntY += hokf;
        float ay = hokf * (1.f - dy), by = hokf * dy;
        WY0 += ((ry1 == 0) ? ay : 0.f) + ((ry2 == 0) ? by : 0.f);
        WY1 += ((ry1 == 1) ? ay : 0.f) + ((ry2 == 1) ? by : 0.f);
        WY2 += ((ry1 == 2) ? ay : 0.f) + ((ry2 == 2) ? by : 0.f);
        float cy = (hok && yv) ? (1.f - dy) : 0.f;
        CY0 += (ry1 == 0) ? cy : 0.f;
        CY1 += (ry1 == 1) ? cy : 0.f;
        CY2 += (ry1 == 2) ? cy : 0.f;
    }

    // ---- X pass (4 iters) ----
    float WX0 = 0.f, WX1 = 0.f, WX2 = 0.f;
    float CX0 = 0.f, CX1 = 0.f, CX2 = 0.f;
    float cntX = 0.f;
#pragma unroll
    for (int iw = 0; iw < 4; iw++) {
        float w = wstart + ((float)iw + 0.5f) * sub_w;
        bool wok = (w > -1.f) && (w < (float)WW);
        float x1f = floorf(w), x2f = ceilf(w);
        bool badx = !((x1f >= 0.f) && (x1f < (float)WW)) ||
                    !((x2f >= 0.f) && (x2f < (float)WW));
        float x1c = fminf(fmaxf(x1f, 0.f), 33.f);
        float x2c = fminf(fmaxf(x2f, 0.f), 33.f);
        float dx = w - x1c;                  // clipped x1 (matches reference)
        int cx1 = (int)x1c - X0;
        int cx2 = (int)x2c - X0;
        float wokf = wok ? 1.f : 0.f;
        cntX += wokf;
        float ax = wokf * (1.f - dx), bx = wokf * dx;
        WX0 += ((cx1 == 0) ? ax : 0.f) + ((cx2 == 0) ? bx : 0.f);
        WX1 += ((cx1 == 1) ? ax : 0.f) + ((cx2 == 1) ? bx : 0.f);
        WX2 += ((cx1 == 2) ? ax : 0.f) + ((cx2 == 2) ? bx : 0.f);
        float cx = (wok && badx) ? (1.f - dx) : 0.f;
        CX0 += (cx1 == 0) ? cx : 0.f;
        CX1 += (cx1 == 1) ? cx : 0.f;
        CX2 += (cx1 == 2) ? cx : 0.f;
    }

    // ---- combine: W9 = WY (x) WX - CY (x) CX ; normalize by cnt ----
    float cnt = cntY * cntX;
    float inv = (cnt > 0.f) ? (1.f / cnt) : 1.f;
    float wy0 = WY0 * inv, wy1 = WY1 * inv, wy2 = WY2 * inv;
    float W9[9];
    W9[0] = fmaf(wy0, WX0, -CY0 * CX0 * inv);
    W9[1] = fmaf(wy0, WX1, -CY0 * CX1 * inv);
    W9[2] = fmaf(wy0, WX2, -CY0 * CX2 * inv);
    W9[3] = fmaf(wy1, WX0, -CY1 * CX0 * inv);
    W9[4] = fmaf(wy1, WX1, -CY1 * CX1 * inv);
    W9[5] = fmaf(wy1, WX2, -CY1 * CX2 * inv);
    W9[6] = fmaf(wy2, WX0, -CY2 * CX0 * inv);
    W9[7] = fmaf(wy2, WX1, -CY2 * CX1 * inv);
    W9[8] = fmaf(wy2, WX2, -CY2 * CX2 * inv);

    // ---- apply stencil: up to 9 texels x 10 channels from shared memory ----
    float a[CC];
#pragma unroll
    for (int i = 0; i < CC; i++) a[i] = 0.f;
    const float* base = sm + (Y0 * WW + X0) * CC;
#pragma unroll
    for (int r = 0; r < 3; r++) {
#pragma unroll
        for (int c2 = 0; c2 < 3; c2++) {
            float wgt = W9[r * 3 + c2];
            if (wgt != 0.f) {                // zero-weight rows/cols skipped
                const float* t = base + (r * WW + c2) * CC;   // 8B-aligned
                float2 v0 = *reinterpret_cast<const float2*>(t + 0);
                float2 v1 = *reinterpret_cast<const float2*>(t + 2);
                float2 v2 = *reinterpret_cast<const float2*>(t + 4);
                float2 v3 = *reinterpret_cast<const float2*>(t + 6);
                float2 v4 = *reinterpret_cast<const float2*>(t + 8);
                a[0] = fmaf(wgt, v0.x, a[0]); a[1] = fmaf(wgt, v0.y, a[1]);
                a[2] = fmaf(wgt, v1.x, a[2]); a[3] = fmaf(wgt, v1.y, a[3]);
                a[4] = fmaf(wgt, v2.x, a[4]); a[5] = fmaf(wgt, v2.y, a[5]);
                a[6] = fmaf(wgt, v3.x, a[6]); a[7] = fmaf(wgt, v3.y, a[7]);
                a[8] = fmaf(wgt, v4.x, a[8]); a[9] = fmaf(wgt, v4.y, a[9]);
            }
        }
    }

    // Coalesced store to scratch [c*49+bin][n]
#pragma unroll
    for (int c2 = 0; c2 < CC; c2++)
        g_out_t[(c2 * NBIN + bin) * N + n] = a[c2];
}

// ---------------------------------------------------------------------------
// Kernel C: tiled transpose scratch[k][n] -> out[n][k]   (k = c*49+bin)
// ---------------------------------------------------------------------------
__global__ void k_transpose_out(float* __restrict__ out, int N) {
    __shared__ float tile[32][33];
    int n0 = blockIdx.x * 32;
    int k0 = blockIdx.y * 32;
    int tx = threadIdx.x, ty = threadIdx.y;
#pragma unroll
    for (int i = 0; i < 32; i += 8) {
        int k = k0 + ty + i, n = n0 + tx;
        if (k < KDIM && n < N) tile[ty + i][tx] = g_out_t[k * N + n];
    }
    __syncthreads();
#pragma unroll
    for (int i = 0; i < 32; i += 8) {
        int n = n0 + ty + i, k = k0 + tx;
        if (n < N && k < KDIM) out[n * KDIM + k] = tile[tx][ty + i];
    }
}

// ---------------------------------------------------------------------------
extern "C" void kernel_launch(void* const* d_in, const int* in_sizes, int n_in,
                              void* d_out, int out_size) {
    const float* ft   = (const float*)d_in[0];
    const float* rois = (const float*)d_in[1];
    float*       out  = (float*)d_out;
    int N = in_sizes[1] / 5;
    if (N > NMAX) N = NMAX;

    dim3 gb((N + BLK - 1) / BLK, NBIN);
    k_roi<<<gb, BLK>>>(ft, rois, N);

    dim3 gc((N + 31) / 32, (KDIM + 31) / 32);
    k_transpose_out<<<gc, dim3(32, 8)>>>(out, N);
}

// round 4
// speedup vs baseline: 1.2439x; 1.2439x over previous
#include <cuda_runtime.h>

#define CC   10
#define NBIN 49
#define HH   34
#define WW   34
#define HW   (HH * WW)          // 1156
#define HW4  (HW / 4)           // 289
#define SLICE (HW * CC)         // 11560 floats = 46240 B
#define KDIM (CC * NBIN)        // 490
#define NMAX 30000
#define BLK  512
#define TILES 4

// Scratch (static device allocation is allowed)
__device__ float g_out_t[KDIM * NMAX];     // [k = c*49+bin][n]

// ---------------------------------------------------------------------------
// Kernel B: one block = (bin, 4 roi-tiles of 512).
// smem layout [c][pos]: the bin's slice is 10 contiguous 4624B chunks of ft,
// so staging is a pure float4 copy (coalesced, conflict-free, no transpose).
// Separable stencil: W9 = WY (x) WX - CY (x) CX, cnt = cntY*cntX.
// ---------------------------------------------------------------------------
__global__ __launch_bounds__(BLK) void k_roi(const float* __restrict__ ft,
                                             const float* __restrict__ rois, int N) {
    __shared__ float sm[SLICE];            // [c][y*34+x]
    const int bin = blockIdx.y;

    // Stage: sm[c*1156 + p] = ft[(c*49+bin)*1156 + p], vectorized.
    {
        float4* dst = reinterpret_cast<float4*>(sm);
        for (int i = threadIdx.x; i < SLICE / 4; i += BLK) {
            int c  = i / HW4;
            int p4 = i - c * HW4;
            dst[i] = reinterpret_cast<const float4*>(ft + (c * NBIN + bin) * HW)[p4];
        }
    }
    __syncthreads();

    const int ph = bin / 7, pw = bin % 7;

#pragma unroll 1
    for (int tile = 0; tile < TILES; tile++) {
        const int n = (blockIdx.x * TILES + tile) * BLK + threadIdx.x;
        if (n >= N) break;

        float rsw = __ldg(rois + n * 5 + 1) * 0.125f;
        float rsh = __ldg(rois + n * 5 + 2) * 0.125f;
        float rew = __ldg(rois + n * 5 + 3) * 0.125f;
        float reh = __ldg(rois + n * 5 + 4) * 0.125f;
        float rh = reh - rsh; rh = (rh > 0.1f) ? rh : 0.1f;
        float rw = rew - rsw; rw = (rw > 0.1f) ? rw : 0.1f;
        float bsh = rh / 7.0f, bsw = rw / 7.0f;
        float sub_h = bsh * 0.25f, sub_w = bsw * 0.25f;
        float hstart = floorf(rsh + (float)ph * bsh);
        float wstart = floorf(rsw + (float)pw * bsw);

        // 3x3 window anchor; all clipped taps land in [X0..X0+2]x[Y0..Y0+2].
        const int X0 = (int)fminf(fmaxf(wstart, 0.f), (float)(WW - 3));
        const int Y0 = (int)fminf(fmaxf(hstart, 0.f), (float)(HH - 3));

        // ---- Y pass ----
        float WY0 = 0.f, WY1 = 0.f, WY2 = 0.f;
        float CY0 = 0.f, CY1 = 0.f, CY2 = 0.f;
        float cntY = 0.f;
#pragma unroll
        for (int ih = 0; ih < 4; ih++) {
            float h = hstart + ((float)ih + 0.5f) * sub_h;
            bool hok = (h > -1.f) && (h < (float)HH);
            float y1f = floorf(h), y2f = ceilf(h);
            bool yv = ((y1f >= 0.f) && (y1f < (float)HH)) ||
                      ((y2f >= 0.f) && (y2f < (float)HH));
            float y1c = fminf(fmaxf(y1f, 0.f), 33.f);
            float y2c = fminf(fmaxf(y2f, 0.f), 33.f);
            float dy = h - y1c;              // clipped y1 (matches reference)
            int ry1 = (int)y1c - Y0;
            int ry2 = (int)y2c - Y0;
            float hokf = hok ? 1.f : 0.f;
            cntY += hokf;
            float ay = hokf * (1.f - dy), by = hokf * dy;
            WY0 += ((ry1 == 0) ? ay : 0.f) + ((ry2 == 0) ? by : 0.f);
            WY1 += ((ry1 == 1) ? ay : 0.f) + ((ry2 == 1) ? by : 0.f);
            WY2 += ((ry1 == 2) ? ay : 0.f) + ((ry2 == 2) ? by : 0.f);
            float cy = (hok && yv) ? (1.f - dy) : 0.f;
            CY0 += (ry1 == 0) ? cy : 0.f;
            CY1 += (ry1 == 1) ? cy : 0.f;
            CY2 += (ry1 == 2) ? cy : 0.f;
        }

        // ---- X pass ----
        float WX0 = 0.f, WX1 = 0.f, WX2 = 0.f;
        float CX0 = 0.f, CX1 = 0.f, CX2 = 0.f;
        float cntX = 0.f;
#pragma unroll
        for (int iw = 0; iw < 4; iw++) {
            float w = wstart + ((float)iw + 0.5f) * sub_w;
            bool wok = (w > -1.f) && (w < (float)WW);
            float x1f = floorf(w), x2f = ceilf(w);
            bool badx = !((x1f >= 0.f) && (x1f < (float)WW)) ||
                        !((x2f >= 0.f) && (x2f < (float)WW));
            float x1c = fminf(fmaxf(x1f, 0.f), 33.f);
            float x2c = fminf(fmaxf(x2f, 0.f), 33.f);
            float dx = w - x1c;              // clipped x1 (matches reference)
            int cx1 = (int)x1c - X0;
            int cx2 = (int)x2c - X0;
            float wokf = wok ? 1.f : 0.f;
            cntX += wokf;
            float ax = wokf * (1.f - dx), bx = wokf * dx;
            WX0 += ((cx1 == 0) ? ax : 0.f) + ((cx2 == 0) ? bx : 0.f);
            WX1 += ((cx1 == 1) ? ax : 0.f) + ((cx2 == 1) ? bx : 0.f);
            WX2 += ((cx1 == 2) ? ax : 0.f) + ((cx2 == 2) ? bx : 0.f);
            float cx = (wok && badx) ? (1.f - dx) : 0.f;
            CX0 += (cx1 == 0) ? cx : 0.f;
            CX1 += (cx1 == 1) ? cx : 0.f;
            CX2 += (cx1 == 2) ? cx : 0.f;
        }

        // ---- combine + normalize ----
        float cnt = cntY * cntX;
        float inv = (cnt > 0.f) ? (1.f / cnt) : 1.f;
        float wy0 = WY0 * inv, wy1 = WY1 * inv, wy2 = WY2 * inv;
        float W9[9];
        W9[0] = fmaf(wy0, WX0, -CY0 * CX0 * inv);
        W9[1] = fmaf(wy0, WX1, -CY0 * CX1 * inv);
        W9[2] = fmaf(wy0, WX2, -CY0 * CX2 * inv);
        W9[3] = fmaf(wy1, WX0, -CY1 * CX0 * inv);
        W9[4] = fmaf(wy1, WX1, -CY1 * CX1 * inv);
        W9[5] = fmaf(wy1, WX2, -CY1 * CX2 * inv);
        W9[6] = fmaf(wy2, WX0, -CY2 * CX0 * inv);
        W9[7] = fmaf(wy2, WX1, -CY2 * CX1 * inv);
        W9[8] = fmaf(wy2, WX2, -CY2 * CX2 * inv);

        // ---- apply stencil from smem [c][pos] ----
        float a[CC];
#pragma unroll
        for (int i = 0; i < CC; i++) a[i] = 0.f;
        const int pbase = Y0 * WW + X0;
#pragma unroll
        for (int r = 0; r < 3; r++) {
#pragma unroll
            for (int c2 = 0; c2 < 3; c2++) {
                float wgt = W9[r * 3 + c2];
                if (wgt != 0.f) {            // zero-weight rows/cols skipped
                    int p = pbase + r * WW + c2;
#pragma unroll
                    for (int c = 0; c < CC; c++)
                        a[c] = fmaf(wgt, sm[c * HW + p], a[c]);
                }
            }
        }

        // Coalesced store to scratch [c*49+bin][n]
#pragma unroll
        for (int c = 0; c < CC; c++)
            g_out_t[(c * NBIN + bin) * N + n] = a[c];
    }
}

// ---------------------------------------------------------------------------
// Kernel C: tiled transpose scratch[k][n] -> out[n][k]   (k = c*49+bin)
// ---------------------------------------------------------------------------
__global__ void k_transpose_out(float* __restrict__ out, int N) {
    __shared__ float tile[32][33];
    int n0 = blockIdx.x * 32;
    int k0 = blockIdx.y * 32;
    int tx = threadIdx.x, ty = threadIdx.y;
#pragma unroll
    for (int i = 0; i < 32; i += 8) {
        int k = k0 + ty + i, n = n0 + tx;
        if (k < KDIM && n < N) tile[ty + i][tx] = g_out_t[k * N + n];
    }
    __syncthreads();
#pragma unroll
    for (int i = 0; i < 32; i += 8) {
        int n = n0 + ty + i, k = k0 + tx;
        if (n < N && k < KDIM) out[n * KDIM + k] = tile[tx][ty + i];
    }
}

// ---------------------------------------------------------------------------
extern "C" void kernel_launch(void* const* d_in, const int* in_sizes, int n_in,
                              void* d_out, int out_size) {
    const float* ft   = (const float*)d_in[0];
    const float* rois = (const float*)d_in[1];
    float*       out  = (float*)d_out;
    int N = in_sizes[1] / 5;
    if (N > NMAX) N = NMAX;

    dim3 gb((N + BLK * TILES - 1) / (BLK * TILES), NBIN);
    k_roi<<<gb, BLK>>>(ft, rois, N);

    dim3 gc((N + 31) / 32, (KDIM + 31) / 32);
    k_transpose_out<<<gc, dim3(32, 8)>>>(out, N);
}

// round 5
// speedup vs baseline: 1.2959x; 1.0418x over previous
#include <cuda_runtime.h>

#define CC    10
#define NBIN  49
#define HH    34
#define WW    34
#define HW    (HH * WW)          // 1156
#define KDIM  (CC * NBIN)        // 490
#define NMAX  30000
#define BLK   512
#define TILES 4

// Scratch (static device allocations are allowed)
__device__ float  g_out_t[KDIM * NMAX];      // [k = c*49+bin][n]
__device__ float4 g_ft8[NBIN * HW * 2];      // [bin][pos][c0..7] as 2x float4
__device__ float2 g_ft2[NBIN * HW];          // [bin][pos][c8..9]

// ---------------------------------------------------------------------------
// Kernel A: ft (C*49, 34, 34) -> channel-interleaved per-bin slices.
// ---------------------------------------------------------------------------
__global__ void k_prep(const float* __restrict__ ft) {
    int idx = blockIdx.x * blockDim.x + threadIdx.x;   // over 49*1156
    if (idx >= NBIN * HW) return;
    int bin = idx / HW;
    int p   = idx - bin * HW;
    const float* s = ft + bin * HW + p;
    float4 v0, v1; float2 v2;
    v0.x = s[0 * NBIN * HW]; v0.y = s[1 * NBIN * HW];
    v0.z = s[2 * NBIN * HW]; v0.w = s[3 * NBIN * HW];
    v1.x = s[4 * NBIN * HW]; v1.y = s[5 * NBIN * HW];
    v1.z = s[6 * NBIN * HW]; v1.w = s[7 * NBIN * HW];
    v2.x = s[8 * NBIN * HW]; v2.y = s[9 * NBIN * HW];
    g_ft8[idx * 2 + 0] = v0;
    g_ft8[idx * 2 + 1] = v1;
    g_ft2[idx]         = v2;
}

// ---------------------------------------------------------------------------
// Kernel B: one block = (bin, TILES roi-tiles). Vectorized smem gather.
// ---------------------------------------------------------------------------
__global__ __launch_bounds__(BLK) void k_roi(const float* __restrict__ rois, int N) {
    __shared__ float4 smA[HW * 2];   // [pos][c0..7]
    __shared__ float2 smB[HW];       // [pos][c8..9]
    const int bin = blockIdx.y;

    {   // stage: contiguous float4 copies, conflict-free
        const float4* s8 = g_ft8 + bin * HW * 2;
        const float4* s2 = reinterpret_cast<const float4*>(g_ft2 + bin * HW);
        float4* d2 = reinterpret_cast<float4*>(smB);
        for (int i = threadIdx.x; i < HW * 2; i += BLK) smA[i] = s8[i];
        for (int i = threadIdx.x; i < HW / 2; i += BLK) d2[i] = s2[i];
    }
    __syncthreads();

    const int ph = bin / 7, pw = bin % 7;

#pragma unroll 1
    for (int tile = 0; tile < TILES; tile++) {
        const int n = (blockIdx.x * TILES + tile) * BLK + threadIdx.x;
        if (n >= N) break;

        float rsw = __ldg(rois + n * 5 + 1) * 0.125f;
        float rsh = __ldg(rois + n * 5 + 2) * 0.125f;
        float rew = __ldg(rois + n * 5 + 3) * 0.125f;
        float reh = __ldg(rois + n * 5 + 4) * 0.125f;
        float rh = reh - rsh; rh = (rh > 0.1f) ? rh : 0.1f;
        float rw = rew - rsw; rw = (rw > 0.1f) ? rw : 0.1f;
        float bsh = rh / 7.0f, bsw = rw / 7.0f;
        float sub_h = bsh * 0.25f, sub_w = bsw * 0.25f;
        float hstart = floorf(rsh + (float)ph * bsh);
        float wstart = floorf(rsw + (float)pw * bsw);

        const int X0 = (int)fminf(fmaxf(wstart, 0.f), (float)(WW - 3));
        const int Y0 = (int)fminf(fmaxf(hstart, 0.f), (float)(HH - 3));

        // ---- Y pass ----
        float WY0 = 0.f, WY1 = 0.f, WY2 = 0.f;
        float CY0 = 0.f, CY1 = 0.f, CY2 = 0.f;
        float cntY = 0.f;
#pragma unroll
        for (int ih = 0; ih < 4; ih++) {
            float h = hstart + ((float)ih + 0.5f) * sub_h;
            bool hok = (h > -1.f) && (h < (float)HH);
            float y1f = floorf(h), y2f = ceilf(h);
            bool yv = ((y1f >= 0.f) && (y1f < (float)HH)) ||
                      ((y2f >= 0.f) && (y2f < (float)HH));
            float y1c = fminf(fmaxf(y1f, 0.f), 33.f);
            float y2c = fminf(fmaxf(y2f, 0.f), 33.f);
            float dy = h - y1c;
            int ry1 = (int)y1c - Y0;
            int ry2 = (int)y2c - Y0;
            float hokf = hok ? 1.f : 0.f;
            cntY += hokf;
            float ay = hokf * (1.f - dy), by = hokf * dy;
            WY0 += ((ry1 == 0) ? ay : 0.f) + ((ry2 == 0) ? by : 0.f);
            WY1 += ((ry1 == 1) ? ay : 0.f) + ((ry2 == 1) ? by : 0.f);
            WY2 += ((ry1 == 2) ? ay : 0.f) + ((ry2 == 2) ? by : 0.f);
            float cy = (hok && yv) ? (1.f - dy) : 0.f;
            CY0 += (ry1 == 0) ? cy : 0.f;
            CY1 += (ry1 == 1) ? cy : 0.f;
            CY2 += (ry1 == 2) ? cy : 0.f;
        }

        // ---- X pass ----
        float WX0 = 0.f, WX1 = 0.f, WX2 = 0.f;
        float CX0 = 0.f, CX1 = 0.f, CX2 = 0.f;
        float cntX = 0.f;
#pragma unroll
        for (int iw = 0; iw < 4; iw++) {
            float w = wstart + ((float)iw + 0.5f) * sub_w;
            bool wok = (w > -1.f) && (w < (float)WW);
            float x1f = floorf(w), x2f = ceilf(w);
            bool badx = !((x1f >= 0.f) && (x1f < (float)WW)) ||
                        !((x2f >= 0.f) && (x2f < (float)WW));
            float x1c = fminf(fmaxf(x1f, 0.f), 33.f);
            float x2c = fminf(fmaxf(x2f, 0.f), 33.f);
            float dx = w - x1c;
            int cx1 = (int)x1c - X0;
            int cx2 = (int)x2c - X0;
            float wokf = wok ? 1.f : 0.f;
            cntX += wokf;
            float ax = wokf * (1.f - dx), bx = wokf * dx;
            WX0 += ((cx1 == 0) ? ax : 0.f) + ((cx2 == 0) ? bx : 0.f);
            WX1 += ((cx1 == 1) ? ax : 0.f) + ((cx2 == 1) ? bx : 0.f);
            WX2 += ((cx1 == 2) ? ax : 0.f) + ((cx2 == 2) ? bx : 0.f);
            float cx = (wok && badx) ? (1.f - dx) : 0.f;
            CX0 += (cx1 == 0) ? cx : 0.f;
            CX1 += (cx1 == 1) ? cx : 0.f;
            CX2 += (cx1 == 2) ? cx : 0.f;
        }

        // ---- combine + normalize ----
        float cnt = cntY * cntX;
        float inv = (cnt > 0.f) ? (1.f / cnt) : 1.f;
        float wy0 = WY0 * inv, wy1 = WY1 * inv, wy2 = WY2 * inv;
        float W00 = fmaf(wy0, WX0, -CY0 * CX0 * inv);
        float W01 = fmaf(wy0, WX1, -CY0 * CX1 * inv);
        float W02 = fmaf(wy0, WX2, -CY0 * CX2 * inv);
        float W10 = fmaf(wy1, WX0, -CY1 * CX0 * inv);
        float W11 = fmaf(wy1, WX1, -CY1 * CX1 * inv);
        float W12 = fmaf(wy1, WX2, -CY1 * CX2 * inv);
        float W20 = fmaf(wy2, WX0, -CY2 * CX0 * inv);
        float W21 = fmaf(wy2, WX1, -CY2 * CX1 * inv);
        float W22 = fmaf(wy2, WX2, -CY2 * CX2 * inv);

        float a0=0.f,a1=0.f,a2=0.f,a3=0.f,a4=0.f,a5=0.f,a6=0.f,a7=0.f,a8=0.f,a9=0.f;
        const int pbase = Y0 * WW + X0;

#define TEXEL(WGT, P) do {                                                  \
            float4 u0 = smA[(P) * 2];                                       \
            float4 u1 = smA[(P) * 2 + 1];                                   \
            float2 u2 = smB[(P)];                                           \
            a0 = fmaf((WGT), u0.x, a0); a1 = fmaf((WGT), u0.y, a1);         \
            a2 = fmaf((WGT), u0.z, a2); a3 = fmaf((WGT), u0.w, a3);         \
            a4 = fmaf((WGT), u1.x, a4); a5 = fmaf((WGT), u1.y, a5);         \
            a6 = fmaf((WGT), u1.z, a6); a7 = fmaf((WGT), u1.w, a7);         \
            a8 = fmaf((WGT), u2.x, a8); a9 = fmaf((WGT), u2.y, a9);         \
        } while (0)

        // unconditional 2x2 core (zero weights contribute 0, harmless)
        TEXEL(W00, pbase);
        TEXEL(W01, pbase + 1);
        TEXEL(W10, pbase + WW);
        TEXEL(W11, pbase + WW + 1);

        bool colx = (W02 != 0.f) || (W12 != 0.f) || (W22 != 0.f);
        bool rowx = (W20 != 0.f) || (W21 != 0.f) || (W22 != 0.f);
        if (colx) { TEXEL(W02, pbase + 2); TEXEL(W12, pbase + WW + 2); }
        if (rowx) { TEXEL(W20, pbase + 2 * WW); TEXEL(W21, pbase + 2 * WW + 1); }
        if (colx && rowx) { TEXEL(W22, pbase + 2 * WW + 2); }
#undef TEXEL

        // Coalesced store to scratch [c*49+bin][n]
        g_out_t[(0 * NBIN + bin) * N + n] = a0;
        g_out_t[(1 * NBIN + bin) * N + n] = a1;
        g_out_t[(2 * NBIN + bin) * N + n] = a2;
        g_out_t[(3 * NBIN + bin) * N + n] = a3;
        g_out_t[(4 * NBIN + bin) * N + n] = a4;
        g_out_t[(5 * NBIN + bin) * N + n] = a5;
        g_out_t[(6 * NBIN + bin) * N + n] = a6;
        g_out_t[(7 * NBIN + bin) * N + n] = a7;
        g_out_t[(8 * NBIN + bin) * N + n] = a8;
        g_out_t[(9 * NBIN + bin) * N + n] = a9;
    }
}

// ---------------------------------------------------------------------------
// Kernel C: vectorized tiled transpose scratch[k][n] -> out[n][k].
// Tile = 32 k x 64 n. float4 loads along n, float2 stores along k.
// Smem pad 69 -> conflict-free in both phases. nbase shifts the n-origin so
// the grid can be split into two launches.
// ---------------------------------------------------------------------------
__global__ void k_transpose_out(float* __restrict__ out, int N, int nbase) {
    __shared__ float tile[32][69];
    const int n0 = nbase + blockIdx.x * 64;
    const int k0 = blockIdx.y * 32;
    const int tx = threadIdx.x & 15;       // 0..15
    const int ty = threadIdx.x >> 4;       // 0..15

    // load: 32 k-rows x 16 float4 (64 n)
#pragma unroll
    for (int i = 0; i < 2; i++) {
        int k = k0 + ty + 16 * i;
        int n = n0 + tx * 4;
        if (k < KDIM && n < N) {
            float4 v = *reinterpret_cast<const float4*>(&g_out_t[k * N + n]);
            tile[ty + 16 * i][tx * 4 + 0] = v.x;
            tile[ty + 16 * i][tx * 4 + 1] = v.y;
            tile[ty + 16 * i][tx * 4 + 2] = v.z;
            tile[ty + 16 * i][tx * 4 + 3] = v.w;
        }
    }
    __syncthreads();

    // store: 64 n-rows x 16 float2 (32 k)
#pragma unroll
    for (int i = 0; i < 4; i++) {
        int n = n0 + ty + 16 * i;
        int k = k0 + tx * 2;
        if (n < N && k < KDIM) {
            float2 v;
            v.x = tile[tx * 2 + 0][ty + 16 * i];
            v.y = tile[tx * 2 + 1][ty + 16 * i];
            *reinterpret_cast<float2*>(&out[n * KDIM + k]) = v;
        }
    }
}

// ---------------------------------------------------------------------------
extern "C" void kernel_launch(void* const* d_in, const int* in_sizes, int n_in,
                              void* d_out, int out_size) {
    const float* ft   = (const float*)d_in[0];
    const float* rois = (const float*)d_in[1];
    float*       out  = (float*)d_out;
    int N = in_sizes[1] / 5;
    if (N > NMAX) N = NMAX;

    k_prep<<<(NBIN * HW + 255) / 256, 256>>>(ft);

    dim3 gb((N + BLK * TILES - 1) / (BLK * TILES), NBIN);
    k_roi<<<gb, BLK>>>(rois, N);

    // split transpose into two launches (also aligns ncu -s 5 onto k_roi)
    int nhalf = ((N / 2) + 63) & ~63;
    if (nhalf > N) nhalf = N;
    dim3 gc1(nhalf / 64 + ((nhalf % 64) ? 1 : 0), (KDIM + 31) / 32);
    if (nhalf > 0) k_transpose_out<<<dim3((nhalf + 63) / 64, (KDIM + 31) / 32), 256>>>(out, N, 0);
    int nrem = N - nhalf;
    if (nrem > 0) k_transpose_out<<<dim3((nrem + 63) / 64, (KDIM + 31) / 32), 256>>>(out, N, nhalf);
}